// round 5
// baseline (speedup 1.0000x reference)
#include <cuda_runtime.h>

// SCSA fused v4: persistent CTAs (240 x 512thr, occ<=2) + work stealing +
// register-blocked convs + interleaved unit order for phase overlap.
// Unit u: even -> spatial x1 of block u/2; odd -> channel x0 of block u/2.
// Reuse-class L2 footprint ~240*0.5MB = 120MB < 126MB L2.

#define NCTAS   240
#define THREADS 512
#define NUNITS  512

__device__ unsigned int g_counter;
__global__ void reset_counter_k() { g_counter = 0u; }

__device__ __forceinline__ float sigmoidf_(float z) {
    return 1.f / (1.f + __expf(-z));
}
__device__ __forceinline__ float sigapx_(float z) {
    float t;
    asm("tanh.approx.f32 %0, %1;" : "=f"(t) : "f"(z * 0.5f));
    return fmaf(0.5f, t, 0.5f);
}
__device__ __forceinline__ float hswishf_(float z) {
    return z * __saturatef((z + 3.f) * (1.f / 6.f));
}
__device__ __forceinline__ int shuffle_out_ch(int p) {
    return (p < 256) ? (2 * p) : (2 * (p - 256) + 1);
}

__global__ __launch_bounds__(THREADS, 2) void scsa_persistent(
    const float* __restrict__ x,
    const float* __restrict__ cweight, const float* __restrict__ cbias,
    const float* __restrict__ conv1_w, const float* __restrict__ conv1_b,
    const float* __restrict__ gn_g,    const float* __restrict__ gn_b,
    const float* __restrict__ convh_w, const float* __restrict__ convh_b,
    const float* __restrict__ convw_w, const float* __restrict__ convw_b,
    float* __restrict__ out)
{
    __shared__ float s_red[4096];   // xh(0-63)|xw(64-127) per channel; aliased as a_h|a_w
    __shared__ float s_y[4096];
    __shared__ float s_w1[1024], s_wh[1024], s_ww[1024];
    __shared__ float s_b1[32], s_bh[32], s_bw[32], s_gg[32], s_gb[32], s_xs[32];
    __shared__ unsigned s_u;
    float* s_a = s_red;

    const int tid  = threadIdx.x;
    const int wid  = tid >> 5;       // 0..15; warp handles channels 2w, 2w+1
    const int lane = tid & 31;
    const int half = lane >> 4;      // row parity within a 2-row load step
    const int q    = lane & 15;
    const int c0   = 2 * wid, c1 = c0 + 1;
    const int t7   = tid >> 7;       // 0..3 (conv output-block id)
    const int pp   = tid & 127;      // conv position id

    // stage weights once (loop-top __syncthreads publishes them)
    for (int i = tid; i < 1024; i += THREADS) {
        s_w1[i] = conv1_w[i];
        s_wh[i] = convh_w[i];
        s_ww[i] = convw_w[i];
    }
    if (tid < 32) {
        s_b1[tid] = conv1_b[tid]; s_bh[tid] = convh_b[tid]; s_bw[tid] = convw_b[tid];
        s_gg[tid] = gn_g[tid];    s_gb[tid] = gn_b[tid];
    }

    while (true) {
        __syncthreads();
        if (tid == 0) s_u = atomicAdd(&g_counter, 1u);
        __syncthreads();
        const unsigned u = s_u;
        if (u >= NUNITS) return;
        const int bb = (int)(u >> 1);
        const int n = bb >> 3, g = bb & 7;

        if (u & 1u) {
            // ================= channel unit: x0 of block bb =================
            const float4* xa = (const float4*)(x + ((size_t)(n * 512 + g * 64 + c0)) * 4096);
            const float4* xb = xa + 1024;
            float sa = 0.f, sb = 0.f;
            #pragma unroll 4
            for (int t = 0; t < 32; t++) {
                float4 va = xa[t * 32 + lane];
                float4 vb = xb[t * 32 + lane];
                sa += (va.x + va.y) + (va.z + va.w);
                sb += (vb.x + vb.y) + (vb.z + vb.w);
            }
            #pragma unroll
            for (int o = 16; o; o >>= 1) {
                sa += __shfl_xor_sync(0xffffffffu, sa, o);
                sb += __shfl_xor_sync(0xffffffffu, sb, o);
            }
            const float ga = sigmoidf_(cweight[c0] * (sa * (1.f / 4096.f)) + cbias[c0]);
            const float gb = sigmoidf_(cweight[c1] * (sb * (1.f / 4096.f)) + cbias[c1]);

            float4* oa = (float4*)(out + ((size_t)(n * 512 + shuffle_out_ch(g * 64 + c0))) * 4096);
            float4* ob = (float4*)(out + ((size_t)(n * 512 + shuffle_out_ch(g * 64 + c1))) * 4096);
            #pragma unroll 4
            for (int t = 0; t < 32; t++) {
                float4 va = __ldcs(&xa[t * 32 + lane]);
                float4 vb = __ldcs(&xb[t * 32 + lane]);
                va.x *= ga; va.y *= ga; va.z *= ga; va.w *= ga;
                vb.x *= gb; vb.y *= gb; vb.z *= gb; vb.w *= gb;
                __stcs(&oa[t * 32 + lane], va);
                __stcs(&ob[t * 32 + lane], vb);
            }
            continue;
        }

        // ================= spatial unit: x1 of block bb =================
        const float4* xa = (const float4*)(x + ((size_t)(n * 512 + g * 64 + 32 + c0)) * 4096);
        const float4* xb = xa + 1024;

        // ---- Pass A: row/col/total means (2 channels per warp) ----
        float a0 = 0.f, a1 = 0.f, a2 = 0.f, a3 = 0.f;
        float b0 = 0.f, b1 = 0.f, b2 = 0.f, b3 = 0.f;
        float xsa = 0.f, xsb = 0.f;
        #pragma unroll 4
        for (int t = 0; t < 32; t++) {
            float4 va = xa[t * 32 + lane];
            float4 vb = xb[t * 32 + lane];
            a0 += va.x; a1 += va.y; a2 += va.z; a3 += va.w;
            b0 += vb.x; b1 += vb.y; b2 += vb.z; b3 += vb.w;
            float ra = (va.x + va.y) + (va.z + va.w);
            float rb = (vb.x + vb.y) + (vb.z + vb.w);
            xsa += ra; xsb += rb;
            #pragma unroll
            for (int o = 8; o; o >>= 1) {
                ra += __shfl_xor_sync(0xffffffffu, ra, o);
                rb += __shfl_xor_sync(0xffffffffu, rb, o);
            }
            if (q == 0) {
                s_red[c0 * 128 + 2 * t + half] = ra * (1.f / 64.f);
                s_red[c1 * 128 + 2 * t + half] = rb * (1.f / 64.f);
            }
        }
        a0 += __shfl_xor_sync(0xffffffffu, a0, 16);
        a1 += __shfl_xor_sync(0xffffffffu, a1, 16);
        a2 += __shfl_xor_sync(0xffffffffu, a2, 16);
        a3 += __shfl_xor_sync(0xffffffffu, a3, 16);
        b0 += __shfl_xor_sync(0xffffffffu, b0, 16);
        b1 += __shfl_xor_sync(0xffffffffu, b1, 16);
        b2 += __shfl_xor_sync(0xffffffffu, b2, 16);
        b3 += __shfl_xor_sync(0xffffffffu, b3, 16);
        #pragma unroll
        for (int o = 16; o; o >>= 1) {
            xsa += __shfl_xor_sync(0xffffffffu, xsa, o);
            xsb += __shfl_xor_sync(0xffffffffu, xsb, o);
        }
        if (half == 0) {
            const float inv = 1.f / 64.f;
            ((float4*)(s_red + c0 * 128 + 64))[q] = make_float4(a0 * inv, a1 * inv, a2 * inv, a3 * inv);
            ((float4*)(s_red + c1 * 128 + 64))[q] = make_float4(b0 * inv, b1 * inv, b2 * inv, b3 * inv);
        }
        if (lane == 0) {
            s_xs[c0] = xsa * (1.f / 4096.f);
            s_xs[c1] = xsb * (1.f / 4096.f);
        }
        __syncthreads();

        // ---- conv1, register-blocked: 8 outputs (o=k*4+t7) share input column p ----
        {
            float acc[8];
            #pragma unroll
            for (int k = 0; k < 8; k++) acc[k] = s_b1[k * 4 + t7];
            #pragma unroll 4
            for (int i = 0; i < 32; i++) {
                const float xv = s_red[i * 128 + pp];
                #pragma unroll
                for (int k = 0; k < 8; k++)
                    acc[k] = fmaf(s_w1[(k * 4 + t7) * 32 + i], xv, acc[k]);
            }
            #pragma unroll
            for (int k = 0; k < 8; k++) s_y[(k * 4 + t7) * 128 + pp] = acc[k];
        }
        __syncthreads();

        // ---- GroupNorm(128) + h-swish: warp handles channels c0, c1 ----
        #pragma unroll
        for (int cc = 0; cc < 2; cc++) {
            const int c = c0 + cc;
            float* yr = s_y + c * 128;
            float v0 = yr[lane], v1 = yr[lane + 32], v2 = yr[lane + 64], v3 = yr[lane + 96];
            float s1 = (v0 + v1) + (v2 + v3);
            float s2 = fmaf(v0, v0, fmaf(v1, v1, fmaf(v2, v2, v3 * v3)));
            #pragma unroll
            for (int o = 16; o; o >>= 1) {
                s1 += __shfl_xor_sync(0xffffffffu, s1, o);
                s2 += __shfl_xor_sync(0xffffffffu, s2, o);
            }
            const float mu  = s1 * (1.f / 128.f);
            const float var = s2 * (1.f / 128.f) - mu * mu;
            const float gm  = s_gg[c] * rsqrtf(var + 1e-5f);
            const float gc  = fmaf(-mu, gm, s_gb[c]);
            yr[lane]      = hswishf_(fmaf(v0, gm, gc));
            yr[lane + 32] = hswishf_(fmaf(v1, gm, gc));
            yr[lane + 64] = hswishf_(fmaf(v2, gm, gc));
            yr[lane + 96] = hswishf_(fmaf(v3, gm, gc));
        }
        __syncthreads();

        // ---- conv_h/conv_w, register-blocked -> s_a (alias s_red) ----
        {
            const float* w  = (pp < 64) ? s_wh : s_ww;
            const float* bs = (pp < 64) ? s_bh : s_bw;
            float acc[8];
            #pragma unroll
            for (int k = 0; k < 8; k++) acc[k] = bs[k * 4 + t7];
            #pragma unroll 4
            for (int i = 0; i < 32; i++) {
                const float yv = s_y[i * 128 + pp];
                #pragma unroll
                for (int k = 0; k < 8; k++)
                    acc[k] = fmaf(w[(k * 4 + t7) * 32 + i], yv, acc[k]);
            }
            #pragma unroll
            for (int k = 0; k < 8; k++) s_a[(k * 4 + t7) * 128 + pp] = acc[k];
        }
        __syncthreads();

        // ---- Pass B: gate + channel-shuffled store (L2-hit re-read) ----
        const float xs0 = s_xs[c0], xs1 = s_xs[c1];
        float4 awa = ((const float4*)(s_a + c0 * 128 + 64))[q];
        float4 awb = ((const float4*)(s_a + c1 * 128 + 64))[q];
        const float ga0 = awa.x * xs0, ga1 = awa.y * xs0, ga2 = awa.z * xs0, ga3 = awa.w * xs0;
        const float gb0 = awb.x * xs1, gb1 = awb.y * xs1, gb2 = awb.z * xs1, gb3 = awb.w * xs1;
        float4* oa = (float4*)(out + ((size_t)(n * 512 + shuffle_out_ch(g * 64 + 32 + c0))) * 4096);
        float4* ob = (float4*)(out + ((size_t)(n * 512 + shuffle_out_ch(g * 64 + 32 + c1))) * 4096);
        #pragma unroll 4
        for (int t = 0; t < 32; t++) {
            float4 va = __ldcs(&xa[t * 32 + lane]);
            float4 vb = __ldcs(&xb[t * 32 + lane]);
            const float aha = s_a[c0 * 128 + 2 * t + half];
            const float ahb = s_a[c1 * 128 + 2 * t + half];
            va.x *= sigapx_(aha * ga0); va.y *= sigapx_(aha * ga1);
            va.z *= sigapx_(aha * ga2); va.w *= sigapx_(aha * ga3);
            vb.x *= sigapx_(ahb * gb0); vb.y *= sigapx_(ahb * gb1);
            vb.z *= sigapx_(ahb * gb2); vb.w *= sigapx_(ahb * gb3);
            __stcs(&oa[t * 32 + lane], va);
            __stcs(&ob[t * 32 + lane], vb);
        }
    }
}

extern "C" void kernel_launch(void* const* d_in, const int* in_sizes, int n_in,
                              void* d_out, int out_size) {
    const float* x       = (const float*)d_in[0];
    const float* cweight = (const float*)d_in[1];
    const float* cbias   = (const float*)d_in[2];
    const float* conv1_w = (const float*)d_in[3];
    const float* conv1_b = (const float*)d_in[4];
    const float* gn_g    = (const float*)d_in[5];
    const float* gn_b    = (const float*)d_in[6];
    const float* convh_w = (const float*)d_in[7];
    const float* convh_b = (const float*)d_in[8];
    const float* convw_w = (const float*)d_in[9];
    const float* convw_b = (const float*)d_in[10];
    float* out = (float*)d_out;

    reset_counter_k<<<1, 1>>>();
    scsa_persistent<<<NCTAS, THREADS>>>(
        x, cweight, cbias, conv1_w, conv1_b, gn_g, gn_b,
        convh_w, convh_b, convw_w, convw_b, out);
}

// round 6
// speedup vs baseline: 1.1121x; 1.1121x over previous
#include <cuda_runtime.h>

// SCSA fused v5 = v3 skeleton (152 x 1024thr persistent occ-1, work stealing,
// .cs streaming) + next-unit L2 prefetch during MLP + register-blocked convs.
// Live L2 footprint: 152 * (0.5MB current + 0.25MB prefetched) = 114MB < 126MB.

#define NCTAS   152
#define THREADS 1024
#define NUNITS  512

__device__ unsigned int g_counter;
__global__ void reset_counter_k() { g_counter = 0u; }

__device__ __forceinline__ float sigmoidf_(float z) {
    return 1.f / (1.f + __expf(-z));
}
__device__ __forceinline__ float sigapx_(float z) {
    float t;
    asm("tanh.approx.f32 %0, %1;" : "=f"(t) : "f"(z * 0.5f));
    return fmaf(0.5f, t, 0.5f);
}
__device__ __forceinline__ float hswishf_(float z) {
    return z * __saturatef((z + 3.f) * (1.f / 6.f));
}
__device__ __forceinline__ int shuffle_out_ch(int p) {
    return (p < 256) ? (2 * p) : (2 * (p - 256) + 1);
}

// Prefetch first 256KB (2048 lines) of unit u's x-region into L2.
__device__ __forceinline__ void prefetch_unit(const float* __restrict__ x,
                                              unsigned u, int tid) {
    if (u >= NUNITS) return;
    const float* pbase;
    if (u < 256) {
        pbase = x + ((size_t)((int)(u >> 3) * 512 + (int)(u & 7) * 64 + 32)) * 4096;
    } else {
        const int b2 = (int)u - 256;
        pbase = x + ((size_t)((b2 >> 3) * 512 + (b2 & 7) * 64)) * 4096;
    }
    #pragma unroll
    for (int j = 0; j < 2; j++) {
        const float* p = pbase + (size_t)(tid + j * 1024) * 32;
        asm volatile("prefetch.global.L2 [%0];" :: "l"(p));
    }
}

__global__ __launch_bounds__(THREADS, 1) void scsa_persistent(
    const float* __restrict__ x,
    const float* __restrict__ cweight, const float* __restrict__ cbias,
    const float* __restrict__ conv1_w, const float* __restrict__ conv1_b,
    const float* __restrict__ gn_g,    const float* __restrict__ gn_b,
    const float* __restrict__ convh_w, const float* __restrict__ convh_b,
    const float* __restrict__ convw_w, const float* __restrict__ convw_b,
    float* __restrict__ out)
{
    __shared__ float s_red[4096];   // xh(0-63)|xw(64-127) per channel; aliased as a_h|a_w
    __shared__ float s_y[4096];
    __shared__ float s_w1[1024], s_wh[1024], s_ww[1024];
    __shared__ float s_b1[32], s_bh[32], s_bw[32], s_gg[32], s_gb[32], s_xs[32];
    __shared__ unsigned s_u;
    float* s_a = s_red;

    const int tid  = threadIdx.x;
    const int wid  = tid >> 5;       // warp = channel
    const int lane = tid & 31;
    const int half = lane >> 4;      // row parity within a 2-row load step
    const int q    = lane & 15;      // float4 index within a row
    const int t7   = tid >> 7;       // 0..7 conv output-block id
    const int pp   = tid & 127;      // conv position id
    const int c    = wid;

    // stage weights once
    s_w1[tid] = conv1_w[tid];
    s_wh[tid] = convh_w[tid];
    s_ww[tid] = convw_w[tid];
    if (tid < 32) {
        s_b1[tid] = conv1_b[tid]; s_bh[tid] = convh_b[tid]; s_bw[tid] = convw_b[tid];
        s_gg[tid] = gn_g[tid];    s_gb[tid] = gn_b[tid];
    }
    if (tid == 0) s_u = atomicAdd(&g_counter, 1u);
    __syncthreads();
    unsigned u = s_u;

    while (u < NUNITS) {
        __syncthreads();             // prev-unit smem reads done; s_u reads done
        if (tid == 0) s_u = atomicAdd(&g_counter, 1u);   // steal next early

        if (u >= 256) {
            // ================= channel unit: x0 of block u-256 =================
            const int b = (int)u - 256;
            const int n = b >> 3, g = b & 7;
            const float4* xc4 = (const float4*)(x + ((size_t)(n * 512 + g * 64 + c)) * 4096);
            float s = 0.f;
            #pragma unroll
            for (int tt = 0; tt < 32; tt += 4) {
                float4 v0 = xc4[(tt + 0) * 32 + lane];
                float4 v1 = xc4[(tt + 1) * 32 + lane];
                float4 v2 = xc4[(tt + 2) * 32 + lane];
                float4 v3 = xc4[(tt + 3) * 32 + lane];
                s += ((v0.x + v0.y) + (v0.z + v0.w)) + ((v1.x + v1.y) + (v1.z + v1.w))
                   + ((v2.x + v2.y) + (v2.z + v2.w)) + ((v3.x + v3.y) + (v3.z + v3.w));
            }
            #pragma unroll
            for (int o = 16; o; o >>= 1) s += __shfl_xor_sync(0xffffffffu, s, o);
            const float gate = sigmoidf_(cweight[c] * (s * (1.f / 4096.f)) + cbias[c]);

            __syncthreads();                 // publish s_u
            const unsigned unext = s_u;
            prefetch_unit(x, unext, tid);

            float4* od = (float4*)(out + ((size_t)(n * 512 + shuffle_out_ch(g * 64 + c))) * 4096);
            #pragma unroll
            for (int tt = 0; tt < 32; tt += 4) {
                float4 v0 = __ldcs(&xc4[(tt + 0) * 32 + lane]);
                float4 v1 = __ldcs(&xc4[(tt + 1) * 32 + lane]);
                float4 v2 = __ldcs(&xc4[(tt + 2) * 32 + lane]);
                float4 v3 = __ldcs(&xc4[(tt + 3) * 32 + lane]);
                v0.x *= gate; v0.y *= gate; v0.z *= gate; v0.w *= gate;
                v1.x *= gate; v1.y *= gate; v1.z *= gate; v1.w *= gate;
                v2.x *= gate; v2.y *= gate; v2.z *= gate; v2.w *= gate;
                v3.x *= gate; v3.y *= gate; v3.z *= gate; v3.w *= gate;
                __stcs(&od[(tt + 0) * 32 + lane], v0);
                __stcs(&od[(tt + 1) * 32 + lane], v1);
                __stcs(&od[(tt + 2) * 32 + lane], v2);
                __stcs(&od[(tt + 3) * 32 + lane], v3);
            }
            u = unext;
            continue;
        }

        // ================= spatial unit: x1 of block u =================
        const int n = (int)u >> 3, g = (int)u & 7;
        const float4* xc4 = (const float4*)(x + ((size_t)(n * 512 + g * 64 + 32 + c)) * 4096);

        // ---- Pass A: row/col/total means. 4 loads in flight per warp. ----
        float cs0 = 0.f, cs1 = 0.f, cs2 = 0.f, cs3 = 0.f, xs = 0.f;
        #pragma unroll
        for (int tt = 0; tt < 32; tt += 4) {
            float4 v0 = xc4[(tt + 0) * 32 + lane];
            float4 v1 = xc4[(tt + 1) * 32 + lane];
            float4 v2 = xc4[(tt + 2) * 32 + lane];
            float4 v3 = xc4[(tt + 3) * 32 + lane];
            cs0 += (v0.x + v1.x) + (v2.x + v3.x);
            cs1 += (v0.y + v1.y) + (v2.y + v3.y);
            cs2 += (v0.z + v1.z) + (v2.z + v3.z);
            cs3 += (v0.w + v1.w) + (v2.w + v3.w);
            float r0 = (v0.x + v0.y) + (v0.z + v0.w);
            float r1 = (v1.x + v1.y) + (v1.z + v1.w);
            float r2 = (v2.x + v2.y) + (v2.z + v2.w);
            float r3 = (v3.x + v3.y) + (v3.z + v3.w);
            xs += (r0 + r1) + (r2 + r3);
            #pragma unroll
            for (int o = 8; o; o >>= 1) {
                r0 += __shfl_xor_sync(0xffffffffu, r0, o);
                r1 += __shfl_xor_sync(0xffffffffu, r1, o);
                r2 += __shfl_xor_sync(0xffffffffu, r2, o);
                r3 += __shfl_xor_sync(0xffffffffu, r3, o);
            }
            if (q == 0) {
                s_red[c * 128 + 2 * (tt + 0) + half] = r0 * (1.f / 64.f);
                s_red[c * 128 + 2 * (tt + 1) + half] = r1 * (1.f / 64.f);
                s_red[c * 128 + 2 * (tt + 2) + half] = r2 * (1.f / 64.f);
                s_red[c * 128 + 2 * (tt + 3) + half] = r3 * (1.f / 64.f);
            }
        }
        cs0 += __shfl_xor_sync(0xffffffffu, cs0, 16);
        cs1 += __shfl_xor_sync(0xffffffffu, cs1, 16);
        cs2 += __shfl_xor_sync(0xffffffffu, cs2, 16);
        cs3 += __shfl_xor_sync(0xffffffffu, cs3, 16);
        #pragma unroll
        for (int o = 16; o; o >>= 1) xs += __shfl_xor_sync(0xffffffffu, xs, o);
        if (half == 0) {
            ((float4*)(s_red + c * 128 + 64))[q] = make_float4(
                cs0 * (1.f / 64.f), cs1 * (1.f / 64.f),
                cs2 * (1.f / 64.f), cs3 * (1.f / 64.f));
        }
        if (lane == 0) s_xs[c] = xs * (1.f / 4096.f);
        __syncthreads();                 // publish reductions + s_u
        const unsigned unext = s_u;

        // ---- prefetch next unit while the MLP runs (DRAM otherwise idle) ----
        prefetch_unit(x, unext, tid);

        // ---- conv1, register-blocked: 4 outputs (o=k*8+t7) share input column pp ----
        {
            float acc0 = s_b1[t7], acc1 = s_b1[8 + t7], acc2 = s_b1[16 + t7], acc3 = s_b1[24 + t7];
            const int wb = t7 * 32;
            #pragma unroll 8
            for (int i = 0; i < 32; i++) {
                const float xv = s_red[i * 128 + pp];
                acc0 = fmaf(s_w1[wb + i],       xv, acc0);
                acc1 = fmaf(s_w1[wb + 256 + i], xv, acc1);
                acc2 = fmaf(s_w1[wb + 512 + i], xv, acc2);
                acc3 = fmaf(s_w1[wb + 768 + i], xv, acc3);
            }
            s_y[t7 * 128 + pp]          = acc0;
            s_y[(8 + t7) * 128 + pp]    = acc1;
            s_y[(16 + t7) * 128 + pp]   = acc2;
            s_y[(24 + t7) * 128 + pp]   = acc3;
        }
        __syncthreads();

        // ---- GroupNorm(128) + h-swish, warp per channel ----
        {
            float* yr = s_y + c * 128;
            float v0 = yr[lane], v1 = yr[lane + 32], v2 = yr[lane + 64], v3 = yr[lane + 96];
            float s1 = (v0 + v1) + (v2 + v3);
            float s2 = fmaf(v0, v0, fmaf(v1, v1, fmaf(v2, v2, v3 * v3)));
            #pragma unroll
            for (int o = 16; o; o >>= 1) {
                s1 += __shfl_xor_sync(0xffffffffu, s1, o);
                s2 += __shfl_xor_sync(0xffffffffu, s2, o);
            }
            const float mu  = s1 * (1.f / 128.f);
            const float var = s2 * (1.f / 128.f) - mu * mu;
            const float gm  = s_gg[c] * rsqrtf(var + 1e-5f);
            const float gc  = fmaf(-mu, gm, s_gb[c]);
            yr[lane]      = hswishf_(fmaf(v0, gm, gc));
            yr[lane + 32] = hswishf_(fmaf(v1, gm, gc));
            yr[lane + 64] = hswishf_(fmaf(v2, gm, gc));
            yr[lane + 96] = hswishf_(fmaf(v3, gm, gc));
        }
        __syncthreads();

        // ---- conv_h/conv_w, register-blocked -> s_a (alias s_red) ----
        {
            const float* w  = (pp < 64) ? s_wh : s_ww;
            const float* bs = (pp < 64) ? s_bh : s_bw;
            float acc0 = bs[t7], acc1 = bs[8 + t7], acc2 = bs[16 + t7], acc3 = bs[24 + t7];
            const int wb = t7 * 32;
            #pragma unroll 8
            for (int i = 0; i < 32; i++) {
                const float yv = s_y[i * 128 + pp];
                acc0 = fmaf(w[wb + i],       yv, acc0);
                acc1 = fmaf(w[wb + 256 + i], yv, acc1);
                acc2 = fmaf(w[wb + 512 + i], yv, acc2);
                acc3 = fmaf(w[wb + 768 + i], yv, acc3);
            }
            s_a[t7 * 128 + pp]        = acc0;
            s_a[(8 + t7) * 128 + pp]  = acc1;
            s_a[(16 + t7) * 128 + pp] = acc2;
            s_a[(24 + t7) * 128 + pp] = acc3;
        }
        __syncthreads();

        // ---- Pass B: gate + channel-shuffled store (L2-hit re-read) ----
        const float xsv = s_xs[c];
        float4 aw = ((const float4*)(s_a + c * 128 + 64))[q];
        const float g0 = aw.x * xsv, g1 = aw.y * xsv, g2 = aw.z * xsv, g3 = aw.w * xsv;
        float4* od = (float4*)(out + ((size_t)(n * 512 + shuffle_out_ch(g * 64 + 32 + c))) * 4096);
        #pragma unroll
        for (int tt = 0; tt < 32; tt += 4) {
            float4 v0 = __ldcs(&xc4[(tt + 0) * 32 + lane]);
            float4 v1 = __ldcs(&xc4[(tt + 1) * 32 + lane]);
            float4 v2 = __ldcs(&xc4[(tt + 2) * 32 + lane]);
            float4 v3 = __ldcs(&xc4[(tt + 3) * 32 + lane]);
            const float a0 = s_a[c * 128 + 2 * (tt + 0) + half];
            const float a1 = s_a[c * 128 + 2 * (tt + 1) + half];
            const float a2 = s_a[c * 128 + 2 * (tt + 2) + half];
            const float a3 = s_a[c * 128 + 2 * (tt + 3) + half];
            v0.x *= sigapx_(a0 * g0); v0.y *= sigapx_(a0 * g1);
            v0.z *= sigapx_(a0 * g2); v0.w *= sigapx_(a0 * g3);
            v1.x *= sigapx_(a1 * g0); v1.y *= sigapx_(a1 * g1);
            v1.z *= sigapx_(a1 * g2); v1.w *= sigapx_(a1 * g3);
            v2.x *= sigapx_(a2 * g0); v2.y *= sigapx_(a2 * g1);
            v2.z *= sigapx_(a2 * g2); v2.w *= sigapx_(a2 * g3);
            v3.x *= sigapx_(a3 * g0); v3.y *= sigapx_(a3 * g1);
            v3.z *= sigapx_(a3 * g2); v3.w *= sigapx_(a3 * g3);
            __stcs(&od[(tt + 0) * 32 + lane], v0);
            __stcs(&od[(tt + 1) * 32 + lane], v1);
            __stcs(&od[(tt + 2) * 32 + lane], v2);
            __stcs(&od[(tt + 3) * 32 + lane], v3);
        }
        u = unext;
    }
}

extern "C" void kernel_launch(void* const* d_in, const int* in_sizes, int n_in,
                              void* d_out, int out_size) {
    const float* x       = (const float*)d_in[0];
    const float* cweight = (const float*)d_in[1];
    const float* cbias   = (const float*)d_in[2];
    const float* conv1_w = (const float*)d_in[3];
    const float* conv1_b = (const float*)d_in[4];
    const float* gn_g    = (const float*)d_in[5];
    const float* gn_b    = (const float*)d_in[6];
    const float* convh_w = (const float*)d_in[7];
    const float* convh_b = (const float*)d_in[8];
    const float* convw_w = (const float*)d_in[9];
    const float* convw_b = (const float*)d_in[10];
    float* out = (float*)d_out;

    reset_counter_k<<<1, 1>>>();
    scsa_persistent<<<NCTAS, THREADS>>>(
        x, cweight, cbias, conv1_w, conv1_b, gn_g, gn_b,
        convh_w, convh_b, convw_w, convw_b, out);
}

// round 7
// speedup vs baseline: 1.2125x; 1.0903x over previous
#include <cuda_runtime.h>

// SCSA fused v6 = v3 skeleton (152 x 1024thr persistent occ-1, work stealing,
// .cs streaming, NO prefetch) + type-interleaved units + register-blocked convs.
// Unit u: even -> spatial x1 of block u/2, odd -> channel x0 of block u/2.
// ~Half the resident CTAs are always pure-streaming channel units, covering
// the spatial CTAs' MLP dead time. In-flight footprint 152*0.5MB = 76MB.

#define NCTAS   152
#define THREADS 1024
#define NUNITS  512

__device__ unsigned int g_counter;
__global__ void reset_counter_k() { g_counter = 0u; }

__device__ __forceinline__ float sigmoidf_(float z) {
    return 1.f / (1.f + __expf(-z));
}
__device__ __forceinline__ float sigapx_(float z) {
    float t;
    asm("tanh.approx.f32 %0, %1;" : "=f"(t) : "f"(z * 0.5f));
    return fmaf(0.5f, t, 0.5f);
}
__device__ __forceinline__ float hswishf_(float z) {
    return z * __saturatef((z + 3.f) * (1.f / 6.f));
}
__device__ __forceinline__ int shuffle_out_ch(int p) {
    return (p < 256) ? (2 * p) : (2 * (p - 256) + 1);
}

__global__ __launch_bounds__(THREADS, 1) void scsa_persistent(
    const float* __restrict__ x,
    const float* __restrict__ cweight, const float* __restrict__ cbias,
    const float* __restrict__ conv1_w, const float* __restrict__ conv1_b,
    const float* __restrict__ gn_g,    const float* __restrict__ gn_b,
    const float* __restrict__ convh_w, const float* __restrict__ convh_b,
    const float* __restrict__ convw_w, const float* __restrict__ convw_b,
    float* __restrict__ out)
{
    __shared__ float s_red[4096];   // xh(0-63)|xw(64-127) per channel; aliased as a_h|a_w
    __shared__ float s_y[4096];
    __shared__ float s_w1[1024], s_wh[1024], s_ww[1024];
    __shared__ float s_b1[32], s_bh[32], s_bw[32], s_gg[32], s_gb[32], s_xs[32];
    __shared__ unsigned s_u;
    float* s_a = s_red;

    const int tid  = threadIdx.x;
    const int wid  = tid >> 5;       // warp = channel
    const int lane = tid & 31;
    const int half = lane >> 4;      // row parity within a 2-row load step
    const int q    = lane & 15;      // float4 index within a row
    const int t7   = tid >> 7;       // 0..7 conv output-block id
    const int pp   = tid & 127;      // conv position id
    const int c    = wid;

    // stage weights once
    s_w1[tid] = conv1_w[tid];
    s_wh[tid] = convh_w[tid];
    s_ww[tid] = convw_w[tid];
    if (tid < 32) {
        s_b1[tid] = conv1_b[tid]; s_bh[tid] = convh_b[tid]; s_bw[tid] = convw_b[tid];
        s_gg[tid] = gn_g[tid];    s_gb[tid] = gn_b[tid];
    }

    while (true) {
        __syncthreads();                 // smem quiesce + weight publish
        if (tid == 0) s_u = atomicAdd(&g_counter, 1u);
        __syncthreads();
        const unsigned u = s_u;
        if (u >= NUNITS) return;
        const int bb = (int)(u >> 1);
        const int n = bb >> 3, g = bb & 7;

        if (u & 1u) {
            // ================= channel unit: x0 of block bb =================
            const float4* xc4 = (const float4*)(x + ((size_t)(n * 512 + g * 64 + c)) * 4096);
            float s = 0.f;
            #pragma unroll
            for (int tt = 0; tt < 32; tt += 4) {
                float4 v0 = xc4[(tt + 0) * 32 + lane];
                float4 v1 = xc4[(tt + 1) * 32 + lane];
                float4 v2 = xc4[(tt + 2) * 32 + lane];
                float4 v3 = xc4[(tt + 3) * 32 + lane];
                s += ((v0.x + v0.y) + (v0.z + v0.w)) + ((v1.x + v1.y) + (v1.z + v1.w))
                   + ((v2.x + v2.y) + (v2.z + v2.w)) + ((v3.x + v3.y) + (v3.z + v3.w));
            }
            #pragma unroll
            for (int o = 16; o; o >>= 1) s += __shfl_xor_sync(0xffffffffu, s, o);
            const float gate = sigmoidf_(cweight[c] * (s * (1.f / 4096.f)) + cbias[c]);

            float4* od = (float4*)(out + ((size_t)(n * 512 + shuffle_out_ch(g * 64 + c))) * 4096);
            #pragma unroll
            for (int tt = 0; tt < 32; tt += 4) {
                float4 v0 = __ldcs(&xc4[(tt + 0) * 32 + lane]);
                float4 v1 = __ldcs(&xc4[(tt + 1) * 32 + lane]);
                float4 v2 = __ldcs(&xc4[(tt + 2) * 32 + lane]);
                float4 v3 = __ldcs(&xc4[(tt + 3) * 32 + lane]);
                v0.x *= gate; v0.y *= gate; v0.z *= gate; v0.w *= gate;
                v1.x *= gate; v1.y *= gate; v1.z *= gate; v1.w *= gate;
                v2.x *= gate; v2.y *= gate; v2.z *= gate; v2.w *= gate;
                v3.x *= gate; v3.y *= gate; v3.z *= gate; v3.w *= gate;
                __stcs(&od[(tt + 0) * 32 + lane], v0);
                __stcs(&od[(tt + 1) * 32 + lane], v1);
                __stcs(&od[(tt + 2) * 32 + lane], v2);
                __stcs(&od[(tt + 3) * 32 + lane], v3);
            }
            continue;
        }

        // ================= spatial unit: x1 of block bb =================
        const float4* xc4 = (const float4*)(x + ((size_t)(n * 512 + g * 64 + 32 + c)) * 4096);

        // ---- Pass A: row/col/total means. 4 loads in flight per warp. ----
        float cs0 = 0.f, cs1 = 0.f, cs2 = 0.f, cs3 = 0.f, xs = 0.f;
        #pragma unroll
        for (int tt = 0; tt < 32; tt += 4) {
            float4 v0 = xc4[(tt + 0) * 32 + lane];
            float4 v1 = xc4[(tt + 1) * 32 + lane];
            float4 v2 = xc4[(tt + 2) * 32 + lane];
            float4 v3 = xc4[(tt + 3) * 32 + lane];
            cs0 += (v0.x + v1.x) + (v2.x + v3.x);
            cs1 += (v0.y + v1.y) + (v2.y + v3.y);
            cs2 += (v0.z + v1.z) + (v2.z + v3.z);
            cs3 += (v0.w + v1.w) + (v2.w + v3.w);
            float r0 = (v0.x + v0.y) + (v0.z + v0.w);
            float r1 = (v1.x + v1.y) + (v1.z + v1.w);
            float r2 = (v2.x + v2.y) + (v2.z + v2.w);
            float r3 = (v3.x + v3.y) + (v3.z + v3.w);
            xs += (r0 + r1) + (r2 + r3);
            #pragma unroll
            for (int o = 8; o; o >>= 1) {
                r0 += __shfl_xor_sync(0xffffffffu, r0, o);
                r1 += __shfl_xor_sync(0xffffffffu, r1, o);
                r2 += __shfl_xor_sync(0xffffffffu, r2, o);
                r3 += __shfl_xor_sync(0xffffffffu, r3, o);
            }
            if (q == 0) {
                s_red[c * 128 + 2 * (tt + 0) + half] = r0 * (1.f / 64.f);
                s_red[c * 128 + 2 * (tt + 1) + half] = r1 * (1.f / 64.f);
                s_red[c * 128 + 2 * (tt + 2) + half] = r2 * (1.f / 64.f);
                s_red[c * 128 + 2 * (tt + 3) + half] = r3 * (1.f / 64.f);
            }
        }
        cs0 += __shfl_xor_sync(0xffffffffu, cs0, 16);
        cs1 += __shfl_xor_sync(0xffffffffu, cs1, 16);
        cs2 += __shfl_xor_sync(0xffffffffu, cs2, 16);
        cs3 += __shfl_xor_sync(0xffffffffu, cs3, 16);
        #pragma unroll
        for (int o = 16; o; o >>= 1) xs += __shfl_xor_sync(0xffffffffu, xs, o);
        if (half == 0) {
            ((float4*)(s_red + c * 128 + 64))[q] = make_float4(
                cs0 * (1.f / 64.f), cs1 * (1.f / 64.f),
                cs2 * (1.f / 64.f), cs3 * (1.f / 64.f));
        }
        if (lane == 0) s_xs[c] = xs * (1.f / 4096.f);
        __syncthreads();

        // ---- conv1, register-blocked: outputs o = t7, 8+t7, 16+t7, 24+t7 ----
        {
            float acc0 = s_b1[t7], acc1 = s_b1[8 + t7], acc2 = s_b1[16 + t7], acc3 = s_b1[24 + t7];
            const int wb = t7 * 32;
            #pragma unroll 8
            for (int i = 0; i < 32; i++) {
                const float xv = s_red[i * 128 + pp];
                acc0 = fmaf(s_w1[wb + i],       xv, acc0);
                acc1 = fmaf(s_w1[wb + 256 + i], xv, acc1);
                acc2 = fmaf(s_w1[wb + 512 + i], xv, acc2);
                acc3 = fmaf(s_w1[wb + 768 + i], xv, acc3);
            }
            s_y[t7 * 128 + pp]        = acc0;
            s_y[(8 + t7) * 128 + pp]  = acc1;
            s_y[(16 + t7) * 128 + pp] = acc2;
            s_y[(24 + t7) * 128 + pp] = acc3;
        }
        __syncthreads();

        // ---- GroupNorm(128) + h-swish, warp per channel ----
        {
            float* yr = s_y + c * 128;
            float v0 = yr[lane], v1 = yr[lane + 32], v2 = yr[lane + 64], v3 = yr[lane + 96];
            float s1 = (v0 + v1) + (v2 + v3);
            float s2 = fmaf(v0, v0, fmaf(v1, v1, fmaf(v2, v2, v3 * v3)));
            #pragma unroll
            for (int o = 16; o; o >>= 1) {
                s1 += __shfl_xor_sync(0xffffffffu, s1, o);
                s2 += __shfl_xor_sync(0xffffffffu, s2, o);
            }
            const float mu  = s1 * (1.f / 128.f);
            const float var = s2 * (1.f / 128.f) - mu * mu;
            const float gm  = s_gg[c] * rsqrtf(var + 1e-5f);
            const float gc  = fmaf(-mu, gm, s_gb[c]);
            yr[lane]      = hswishf_(fmaf(v0, gm, gc));
            yr[lane + 32] = hswishf_(fmaf(v1, gm, gc));
            yr[lane + 64] = hswishf_(fmaf(v2, gm, gc));
            yr[lane + 96] = hswishf_(fmaf(v3, gm, gc));
        }
        __syncthreads();

        // ---- conv_h/conv_w, register-blocked -> s_a (alias s_red) ----
        {
            const float* w  = (pp < 64) ? s_wh : s_ww;
            const float* bs = (pp < 64) ? s_bh : s_bw;
            float acc0 = bs[t7], acc1 = bs[8 + t7], acc2 = bs[16 + t7], acc3 = bs[24 + t7];
            const int wb = t7 * 32;
            #pragma unroll 8
            for (int i = 0; i < 32; i++) {
                const float yv = s_y[i * 128 + pp];
                acc0 = fmaf(w[wb + i],       yv, acc0);
                acc1 = fmaf(w[wb + 256 + i], yv, acc1);
                acc2 = fmaf(w[wb + 512 + i], yv, acc2);
                acc3 = fmaf(w[wb + 768 + i], yv, acc3);
            }
            s_a[t7 * 128 + pp]        = acc0;
            s_a[(8 + t7) * 128 + pp]  = acc1;
            s_a[(16 + t7) * 128 + pp] = acc2;
            s_a[(24 + t7) * 128 + pp] = acc3;
        }
        __syncthreads();

        // ---- Pass B: gate + channel-shuffled store (L2-hit re-read) ----
        const float xsv = s_xs[c];
        float4 aw = ((const float4*)(s_a + c * 128 + 64))[q];
        const float g0 = aw.x * xsv, g1 = aw.y * xsv, g2 = aw.z * xsv, g3 = aw.w * xsv;
        float4* od = (float4*)(out + ((size_t)(n * 512 + shuffle_out_ch(g * 64 + 32 + c))) * 4096);
        #pragma unroll
        for (int tt = 0; tt < 32; tt += 4) {
            float4 v0 = __ldcs(&xc4[(tt + 0) * 32 + lane]);
            float4 v1 = __ldcs(&xc4[(tt + 1) * 32 + lane]);
            float4 v2 = __ldcs(&xc4[(tt + 2) * 32 + lane]);
            float4 v3 = __ldcs(&xc4[(tt + 3) * 32 + lane]);
            const float a0 = s_a[c * 128 + 2 * (tt + 0) + half];
            const float a1 = s_a[c * 128 + 2 * (tt + 1) + half];
            const float a2 = s_a[c * 128 + 2 * (tt + 2) + half];
            const float a3 = s_a[c * 128 + 2 * (tt + 3) + half];
            v0.x *= sigapx_(a0 * g0); v0.y *= sigapx_(a0 * g1);
            v0.z *= sigapx_(a0 * g2); v0.w *= sigapx_(a0 * g3);
            v1.x *= sigapx_(a1 * g0); v1.y *= sigapx_(a1 * g1);
            v1.z *= sigapx_(a1 * g2); v1.w *= sigapx_(a1 * g3);
            v2.x *= sigapx_(a2 * g0); v2.y *= sigapx_(a2 * g1);
            v2.z *= sigapx_(a2 * g2); v2.w *= sigapx_(a2 * g3);
            v3.x *= sigapx_(a3 * g0); v3.y *= sigapx_(a3 * g1);
            v3.z *= sigapx_(a3 * g2); v3.w *= sigapx_(a3 * g3);
            __stcs(&od[(tt + 0) * 32 + lane], v0);
            __stcs(&od[(tt + 1) * 32 + lane], v1);
            __stcs(&od[(tt + 2) * 32 + lane], v2);
            __stcs(&od[(tt + 3) * 32 + lane], v3);
        }
    }
}

extern "C" void kernel_launch(void* const* d_in, const int* in_sizes, int n_in,
                              void* d_out, int out_size) {
    const float* x       = (const float*)d_in[0];
    const float* cweight = (const float*)d_in[1];
    const float* cbias   = (const float*)d_in[2];
    const float* conv1_w = (const float*)d_in[3];
    const float* conv1_b = (const float*)d_in[4];
    const float* gn_g    = (const float*)d_in[5];
    const float* gn_b    = (const float*)d_in[6];
    const float* convh_w = (const float*)d_in[7];
    const float* convh_b = (const float*)d_in[8];
    const float* convw_w = (const float*)d_in[9];
    const float* convw_b = (const float*)d_in[10];
    float* out = (float*)d_out;

    reset_counter_k<<<1, 1>>>();
    scsa_persistent<<<NCTAS, THREADS>>>(
        x, cweight, cbias, conv1_w, conv1_b, gn_g, gn_b,
        convh_w, convh_b, convw_w, convw_b, out);
}

// round 8
// speedup vs baseline: 1.2425x; 1.0247x over previous
#include <cuda_runtime.h>

// SCSA fused v7 = v6 (152 x 1024thr persistent occ-1, work stealing, type-
// interleaved units, .cs streaming) with ALL global loops unrolled x8:
// 8 LDG.128 in flight per warp -> 32KB in flight per SM (covers DRAM latency
// at fair-share BW; unroll-4's 16KB was the measured ~64% util limiter).

#define NCTAS   152
#define THREADS 1024
#define NUNITS  512

__device__ unsigned int g_counter;
__global__ void reset_counter_k() { g_counter = 0u; }

__device__ __forceinline__ float sigmoidf_(float z) {
    return 1.f / (1.f + __expf(-z));
}
__device__ __forceinline__ float sigapx_(float z) {
    float t;
    asm("tanh.approx.f32 %0, %1;" : "=f"(t) : "f"(z * 0.5f));
    return fmaf(0.5f, t, 0.5f);
}
__device__ __forceinline__ float hswishf_(float z) {
    return z * __saturatef((z + 3.f) * (1.f / 6.f));
}
__device__ __forceinline__ int shuffle_out_ch(int p) {
    return (p < 256) ? (2 * p) : (2 * (p - 256) + 1);
}

__global__ __launch_bounds__(THREADS, 1) void scsa_persistent(
    const float* __restrict__ x,
    const float* __restrict__ cweight, const float* __restrict__ cbias,
    const float* __restrict__ conv1_w, const float* __restrict__ conv1_b,
    const float* __restrict__ gn_g,    const float* __restrict__ gn_b,
    const float* __restrict__ convh_w, const float* __restrict__ convh_b,
    const float* __restrict__ convw_w, const float* __restrict__ convw_b,
    float* __restrict__ out)
{
    __shared__ float s_red[4096];   // xh(0-63)|xw(64-127) per channel; aliased as a_h|a_w
    __shared__ float s_y[4096];
    __shared__ float s_w1[1024], s_wh[1024], s_ww[1024];
    __shared__ float s_b1[32], s_bh[32], s_bw[32], s_gg[32], s_gb[32], s_xs[32];
    __shared__ unsigned s_u;
    float* s_a = s_red;

    const int tid  = threadIdx.x;
    const int wid  = tid >> 5;       // warp = channel
    const int lane = tid & 31;
    const int half = lane >> 4;      // row parity within a 2-row load step
    const int q    = lane & 15;      // float4 index within a row
    const int t7   = tid >> 7;       // 0..7 conv output-block id
    const int pp   = tid & 127;      // conv position id
    const int c    = wid;

    // stage weights once
    s_w1[tid] = conv1_w[tid];
    s_wh[tid] = convh_w[tid];
    s_ww[tid] = convw_w[tid];
    if (tid < 32) {
        s_b1[tid] = conv1_b[tid]; s_bh[tid] = convh_b[tid]; s_bw[tid] = convw_b[tid];
        s_gg[tid] = gn_g[tid];    s_gb[tid] = gn_b[tid];
    }

    while (true) {
        __syncthreads();                 // smem quiesce + weight publish
        if (tid == 0) s_u = atomicAdd(&g_counter, 1u);
        __syncthreads();
        const unsigned u = s_u;
        if (u >= NUNITS) return;
        const int bb = (int)(u >> 1);
        const int n = bb >> 3, g = bb & 7;

        if (u & 1u) {
            // ================= channel unit: x0 of block bb =================
            const float4* xc4 = (const float4*)(x + ((size_t)(n * 512 + g * 64 + c)) * 4096);
            float s = 0.f;
            #pragma unroll
            for (int tt = 0; tt < 32; tt += 8) {
                float4 v[8];
                #pragma unroll
                for (int j = 0; j < 8; j++) v[j] = xc4[(tt + j) * 32 + lane];
                #pragma unroll
                for (int j = 0; j < 8; j++)
                    s += (v[j].x + v[j].y) + (v[j].z + v[j].w);
            }
            #pragma unroll
            for (int o = 16; o; o >>= 1) s += __shfl_xor_sync(0xffffffffu, s, o);
            const float gate = sigmoidf_(cweight[c] * (s * (1.f / 4096.f)) + cbias[c]);

            float4* od = (float4*)(out + ((size_t)(n * 512 + shuffle_out_ch(g * 64 + c))) * 4096);
            #pragma unroll
            for (int tt = 0; tt < 32; tt += 8) {
                float4 v[8];
                #pragma unroll
                for (int j = 0; j < 8; j++) v[j] = __ldcs(&xc4[(tt + j) * 32 + lane]);
                #pragma unroll
                for (int j = 0; j < 8; j++) {
                    v[j].x *= gate; v[j].y *= gate; v[j].z *= gate; v[j].w *= gate;
                    __stcs(&od[(tt + j) * 32 + lane], v[j]);
                }
            }
            continue;
        }

        // ================= spatial unit: x1 of block bb =================
        const float4* xc4 = (const float4*)(x + ((size_t)(n * 512 + g * 64 + 32 + c)) * 4096);

        // ---- Pass A: row/col/total means. 8 loads in flight per warp. ----
        float cs0 = 0.f, cs1 = 0.f, cs2 = 0.f, cs3 = 0.f, xs = 0.f;
        #pragma unroll
        for (int tt = 0; tt < 32; tt += 8) {
            float4 v[8];
            #pragma unroll
            for (int j = 0; j < 8; j++) v[j] = xc4[(tt + j) * 32 + lane];
            float r[8];
            #pragma unroll
            for (int j = 0; j < 8; j++) {
                cs0 += v[j].x; cs1 += v[j].y; cs2 += v[j].z; cs3 += v[j].w;
                r[j] = (v[j].x + v[j].y) + (v[j].z + v[j].w);
                xs += r[j];
            }
            #pragma unroll
            for (int o = 8; o; o >>= 1) {
                #pragma unroll
                for (int j = 0; j < 8; j++)
                    r[j] += __shfl_xor_sync(0xffffffffu, r[j], o);
            }
            if (q == 0) {
                #pragma unroll
                for (int j = 0; j < 8; j++)
                    s_red[c * 128 + 2 * (tt + j) + half] = r[j] * (1.f / 64.f);
            }
        }
        cs0 += __shfl_xor_sync(0xffffffffu, cs0, 16);
        cs1 += __shfl_xor_sync(0xffffffffu, cs1, 16);
        cs2 += __shfl_xor_sync(0xffffffffu, cs2, 16);
        cs3 += __shfl_xor_sync(0xffffffffu, cs3, 16);
        #pragma unroll
        for (int o = 16; o; o >>= 1) xs += __shfl_xor_sync(0xffffffffu, xs, o);
        if (half == 0) {
            ((float4*)(s_red + c * 128 + 64))[q] = make_float4(
                cs0 * (1.f / 64.f), cs1 * (1.f / 64.f),
                cs2 * (1.f / 64.f), cs3 * (1.f / 64.f));
        }
        if (lane == 0) s_xs[c] = xs * (1.f / 4096.f);
        __syncthreads();

        // ---- conv1, register-blocked: outputs o = t7, 8+t7, 16+t7, 24+t7 ----
        {
            float acc0 = s_b1[t7], acc1 = s_b1[8 + t7], acc2 = s_b1[16 + t7], acc3 = s_b1[24 + t7];
            const int wb = t7 * 32;
            #pragma unroll 8
            for (int i = 0; i < 32; i++) {
                const float xv = s_red[i * 128 + pp];
                acc0 = fmaf(s_w1[wb + i],       xv, acc0);
                acc1 = fmaf(s_w1[wb + 256 + i], xv, acc1);
                acc2 = fmaf(s_w1[wb + 512 + i], xv, acc2);
                acc3 = fmaf(s_w1[wb + 768 + i], xv, acc3);
            }
            s_y[t7 * 128 + pp]        = acc0;
            s_y[(8 + t7) * 128 + pp]  = acc1;
            s_y[(16 + t7) * 128 + pp] = acc2;
            s_y[(24 + t7) * 128 + pp] = acc3;
        }
        __syncthreads();

        // ---- GroupNorm(128) + h-swish, warp per channel ----
        {
            float* yr = s_y + c * 128;
            float v0 = yr[lane], v1 = yr[lane + 32], v2 = yr[lane + 64], v3 = yr[lane + 96];
            float s1 = (v0 + v1) + (v2 + v3);
            float s2 = fmaf(v0, v0, fmaf(v1, v1, fmaf(v2, v2, v3 * v3)));
            #pragma unroll
            for (int o = 16; o; o >>= 1) {
                s1 += __shfl_xor_sync(0xffffffffu, s1, o);
                s2 += __shfl_xor_sync(0xffffffffu, s2, o);
            }
            const float mu  = s1 * (1.f / 128.f);
            const float var = s2 * (1.f / 128.f) - mu * mu;
            const float gm  = s_gg[c] * rsqrtf(var + 1e-5f);
            const float gc  = fmaf(-mu, gm, s_gb[c]);
            yr[lane]      = hswishf_(fmaf(v0, gm, gc));
            yr[lane + 32] = hswishf_(fmaf(v1, gm, gc));
            yr[lane + 64] = hswishf_(fmaf(v2, gm, gc));
            yr[lane + 96] = hswishf_(fmaf(v3, gm, gc));
        }
        __syncthreads();

        // ---- conv_h/conv_w, register-blocked -> s_a (alias s_red) ----
        {
            const float* w  = (pp < 64) ? s_wh : s_ww;
            const float* bs = (pp < 64) ? s_bh : s_bw;
            float acc0 = bs[t7], acc1 = bs[8 + t7], acc2 = bs[16 + t7], acc3 = bs[24 + t7];
            const int wb = t7 * 32;
            #pragma unroll 8
            for (int i = 0; i < 32; i++) {
                const float yv = s_y[i * 128 + pp];
                acc0 = fmaf(w[wb + i],       yv, acc0);
                acc1 = fmaf(w[wb + 256 + i], yv, acc1);
                acc2 = fmaf(w[wb + 512 + i], yv, acc2);
                acc3 = fmaf(w[wb + 768 + i], yv, acc3);
            }
            s_a[t7 * 128 + pp]        = acc0;
            s_a[(8 + t7) * 128 + pp]  = acc1;
            s_a[(16 + t7) * 128 + pp] = acc2;
            s_a[(24 + t7) * 128 + pp] = acc3;
        }
        __syncthreads();

        // ---- Pass B: gate + channel-shuffled store (L2-hit re-read) ----
        const float xsv = s_xs[c];
        float4 aw = ((const float4*)(s_a + c * 128 + 64))[q];
        const float g0 = aw.x * xsv, g1 = aw.y * xsv, g2 = aw.z * xsv, g3 = aw.w * xsv;
        float4* od = (float4*)(out + ((size_t)(n * 512 + shuffle_out_ch(g * 64 + 32 + c))) * 4096);
        #pragma unroll
        for (int tt = 0; tt < 32; tt += 8) {
            float4 v[8];
            #pragma unroll
            for (int j = 0; j < 8; j++) v[j] = __ldcs(&xc4[(tt + j) * 32 + lane]);
            #pragma unroll
            for (int j = 0; j < 8; j++) {
                const float ah = s_a[c * 128 + 2 * (tt + j) + half];
                v[j].x *= sigapx_(ah * g0);
                v[j].y *= sigapx_(ah * g1);
                v[j].z *= sigapx_(ah * g2);
                v[j].w *= sigapx_(ah * g3);
                __stcs(&od[(tt + j) * 32 + lane], v[j]);
            }
        }
    }
}

extern "C" void kernel_launch(void* const* d_in, const int* in_sizes, int n_in,
                              void* d_out, int out_size) {
    const float* x       = (const float*)d_in[0];
    const float* cweight = (const float*)d_in[1];
    const float* cbias   = (const float*)d_in[2];
    const float* conv1_w = (const float*)d_in[3];
    const float* conv1_b = (const float*)d_in[4];
    const float* gn_g    = (const float*)d_in[5];
    const float* gn_b    = (const float*)d_in[6];
    const float* convh_w = (const float*)d_in[7];
    const float* convh_b = (const float*)d_in[8];
    const float* convw_w = (const float*)d_in[9];
    const float* convw_b = (const float*)d_in[10];
    float* out = (float*)d_out;

    reset_counter_k<<<1, 1>>>();
    scsa_persistent<<<NCTAS, THREADS>>>(
        x, cweight, cbias, conv1_w, conv1_b, gn_g, gn_b,
        convh_w, convh_b, convw_w, convw_b, out);
}

// round 9
// speedup vs baseline: 1.3908x; 1.1194x over previous
#include <cuda_runtime.h>

// SCSA fused v8 = v7 skeleton (152 x 1024thr persistent occ-1, work stealing,
// .cs streaming, unroll-8) with FINE-GRAINED work units to kill the 19%
// last-wave tail (512/152 = 3.37 -> some CTAs did 4 units, others 3):
//   ids 0..511  : even -> spatial unit (block id/2, weight 1)
//                 odd  -> channel-quarter #(id/2)   (blocks 0..63)
//   ids 512..1279: channel-quarter #(id-256)        (blocks 64..255)
// channel-quarter = 8 channels of a block's x0 half (weight 1/4, 4 per block).
// Greedy steal + big-first ordering bounds the tail at ~a quarter unit (~4%).

#define NCTAS   152
#define THREADS 1024
#define NUNITS  1280

__device__ unsigned int g_counter;
__global__ void reset_counter_k() { g_counter = 0u; }

__device__ __forceinline__ float sigmoidf_(float z) {
    return 1.f / (1.f + __expf(-z));
}
__device__ __forceinline__ float sigapx_(float z) {
    float t;
    asm("tanh.approx.f32 %0, %1;" : "=f"(t) : "f"(z * 0.5f));
    return fmaf(0.5f, t, 0.5f);
}
__device__ __forceinline__ float hswishf_(float z) {
    return z * __saturatef((z + 3.f) * (1.f / 6.f));
}
__device__ __forceinline__ int shuffle_out_ch(int p) {
    return (p < 256) ? (2 * p) : (2 * (p - 256) + 1);
}

__global__ __launch_bounds__(THREADS, 1) void scsa_persistent(
    const float* __restrict__ x,
    const float* __restrict__ cweight, const float* __restrict__ cbias,
    const float* __restrict__ conv1_w, const float* __restrict__ conv1_b,
    const float* __restrict__ gn_g,    const float* __restrict__ gn_b,
    const float* __restrict__ convh_w, const float* __restrict__ convh_b,
    const float* __restrict__ convw_w, const float* __restrict__ convw_b,
    float* __restrict__ out)
{
    __shared__ float s_red[4096];   // xh(0-63)|xw(64-127) per channel; aliased a_h|a_w
    __shared__ float s_y[4096];
    __shared__ float s_w1[1024], s_wh[1024], s_ww[1024];
    __shared__ float s_b1[32], s_bh[32], s_bw[32], s_gg[32], s_gb[32], s_xs[32];
    __shared__ float s_part[32];    // channel-quarter partial sums [ch8*4 + rowblk]
    __shared__ float s_gate[8];
    __shared__ unsigned s_u;
    float* s_a = s_red;

    const int tid  = threadIdx.x;
    const int wid  = tid >> 5;       // warp id
    const int lane = tid & 31;
    const int half = lane >> 4;
    const int q    = lane & 15;
    const int t7   = tid >> 7;       // 0..7 conv output-block id
    const int pp   = tid & 127;      // conv position id
    const int c    = wid;            // spatial: warp = channel

    // stage weights once
    s_w1[tid] = conv1_w[tid];
    s_wh[tid] = convh_w[tid];
    s_ww[tid] = convw_w[tid];
    if (tid < 32) {
        s_b1[tid] = conv1_b[tid]; s_bh[tid] = convh_b[tid]; s_bw[tid] = convw_b[tid];
        s_gg[tid] = gn_g[tid];    s_gb[tid] = gn_b[tid];
    }

    while (true) {
        __syncthreads();                 // smem quiesce + weight publish
        if (tid == 0) s_u = atomicAdd(&g_counter, 1u);
        __syncthreads();
        const unsigned u = s_u;
        if (u >= NUNITS) return;

        // ---------------- unit decode ----------------
        bool is_spatial = (u < 512) && !(u & 1u);
        int bb, qd = 0;
        if (is_spatial) {
            bb = (int)(u >> 1);
        } else {
            const int cq = (u < 512) ? (int)(u >> 1) : (int)(u - 256);
            bb = cq >> 2; qd = cq & 3;
        }
        const int n = bb >> 3, g = bb & 7;

        if (!is_spatial) {
            // ========== channel-quarter: x0 channels g*64 + qd*8 + [0,8) ==========
            // warp w: channel (w&7), row-block (w>>3) (16 rows = 256 float4).
            const int ch8 = wid & 7;
            const int rb  = wid >> 3;
            const int cglob = g * 64 + qd * 8 + ch8;
            const float4* xq4 = (const float4*)(x + ((size_t)(n * 512 + cglob)) * 4096)
                              + rb * 256;
            float s = 0.f;
            {
                float4 v[8];
                #pragma unroll
                for (int j = 0; j < 8; j++) v[j] = xq4[j * 32 + lane];
                #pragma unroll
                for (int j = 0; j < 8; j++)
                    s += (v[j].x + v[j].y) + (v[j].z + v[j].w);
            }
            #pragma unroll
            for (int o = 16; o; o >>= 1) s += __shfl_xor_sync(0xffffffffu, s, o);
            if (lane == 0) s_part[ch8 * 4 + rb] = s;
            __syncthreads();
            if (tid < 8) {
                const float tot = s_part[tid * 4] + s_part[tid * 4 + 1]
                                + s_part[tid * 4 + 2] + s_part[tid * 4 + 3];
                const int cg = g * 64 + qd * 8 + tid;
                s_gate[tid] = sigmoidf_(cweight[cg & 63] * (tot * (1.f / 4096.f))
                                        + cbias[cg & 63]);
            }
            __syncthreads();
            const float gate = s_gate[ch8];
            float4* od = (float4*)(out + ((size_t)(n * 512 + shuffle_out_ch(cglob))) * 4096)
                       + rb * 256;
            {
                float4 v[8];
                #pragma unroll
                for (int j = 0; j < 8; j++) v[j] = __ldcs(&xq4[j * 32 + lane]);
                #pragma unroll
                for (int j = 0; j < 8; j++) {
                    v[j].x *= gate; v[j].y *= gate; v[j].z *= gate; v[j].w *= gate;
                    __stcs(&od[j * 32 + lane], v[j]);
                }
            }
            continue;
        }

        // ================= spatial unit: x1 of block bb =================
        const float4* xc4 = (const float4*)(x + ((size_t)(n * 512 + g * 64 + 32 + c)) * 4096);

        // ---- Pass A: row/col/total means. 8 loads in flight per warp. ----
        float cs0 = 0.f, cs1 = 0.f, cs2 = 0.f, cs3 = 0.f, xs = 0.f;
        #pragma unroll
        for (int tt = 0; tt < 32; tt += 8) {
            float4 v[8];
            #pragma unroll
            for (int j = 0; j < 8; j++) v[j] = xc4[(tt + j) * 32 + lane];
            float r[8];
            #pragma unroll
            for (int j = 0; j < 8; j++) {
                cs0 += v[j].x; cs1 += v[j].y; cs2 += v[j].z; cs3 += v[j].w;
                r[j] = (v[j].x + v[j].y) + (v[j].z + v[j].w);
                xs += r[j];
            }
            #pragma unroll
            for (int o = 8; o; o >>= 1) {
                #pragma unroll
                for (int j = 0; j < 8; j++)
                    r[j] += __shfl_xor_sync(0xffffffffu, r[j], o);
            }
            if (q == 0) {
                #pragma unroll
                for (int j = 0; j < 8; j++)
                    s_red[c * 128 + 2 * (tt + j) + half] = r[j] * (1.f / 64.f);
            }
        }
        cs0 += __shfl_xor_sync(0xffffffffu, cs0, 16);
        cs1 += __shfl_xor_sync(0xffffffffu, cs1, 16);
        cs2 += __shfl_xor_sync(0xffffffffu, cs2, 16);
        cs3 += __shfl_xor_sync(0xffffffffu, cs3, 16);
        #pragma unroll
        for (int o = 16; o; o >>= 1) xs += __shfl_xor_sync(0xffffffffu, xs, o);
        if (half == 0) {
            ((float4*)(s_red + c * 128 + 64))[q] = make_float4(
                cs0 * (1.f / 64.f), cs1 * (1.f / 64.f),
                cs2 * (1.f / 64.f), cs3 * (1.f / 64.f));
        }
        if (lane == 0) s_xs[c] = xs * (1.f / 4096.f);
        __syncthreads();

        // ---- conv1, register-blocked: outputs o = t7, 8+t7, 16+t7, 24+t7 ----
        {
            float acc0 = s_b1[t7], acc1 = s_b1[8 + t7], acc2 = s_b1[16 + t7], acc3 = s_b1[24 + t7];
            const int wb = t7 * 32;
            #pragma unroll 8
            for (int i = 0; i < 32; i++) {
                const float xv = s_red[i * 128 + pp];
                acc0 = fmaf(s_w1[wb + i],       xv, acc0);
                acc1 = fmaf(s_w1[wb + 256 + i], xv, acc1);
                acc2 = fmaf(s_w1[wb + 512 + i], xv, acc2);
                acc3 = fmaf(s_w1[wb + 768 + i], xv, acc3);
            }
            s_y[t7 * 128 + pp]        = acc0;
            s_y[(8 + t7) * 128 + pp]  = acc1;
            s_y[(16 + t7) * 128 + pp] = acc2;
            s_y[(24 + t7) * 128 + pp] = acc3;
        }
        __syncthreads();

        // ---- GroupNorm(128) + h-swish, warp per channel ----
        {
            float* yr = s_y + c * 128;
            float v0 = yr[lane], v1 = yr[lane + 32], v2 = yr[lane + 64], v3 = yr[lane + 96];
            float s1 = (v0 + v1) + (v2 + v3);
            float s2 = fmaf(v0, v0, fmaf(v1, v1, fmaf(v2, v2, v3 * v3)));
            #pragma unroll
            for (int o = 16; o; o >>= 1) {
                s1 += __shfl_xor_sync(0xffffffffu, s1, o);
                s2 += __shfl_xor_sync(0xffffffffu, s2, o);
            }
            const float mu  = s1 * (1.f / 128.f);
            const float var = s2 * (1.f / 128.f) - mu * mu;
            const float gm  = s_gg[c] * rsqrtf(var + 1e-5f);
            const float gc  = fmaf(-mu, gm, s_gb[c]);
            yr[lane]      = hswishf_(fmaf(v0, gm, gc));
            yr[lane + 32] = hswishf_(fmaf(v1, gm, gc));
            yr[lane + 64] = hswishf_(fmaf(v2, gm, gc));
            yr[lane + 96] = hswishf_(fmaf(v3, gm, gc));
        }
        __syncthreads();

        // ---- conv_h/conv_w, register-blocked -> s_a (alias s_red) ----
        {
            const float* w  = (pp < 64) ? s_wh : s_ww;
            const float* bs = (pp < 64) ? s_bh : s_bw;
            float acc0 = bs[t7], acc1 = bs[8 + t7], acc2 = bs[16 + t7], acc3 = bs[24 + t7];
            const int wb = t7 * 32;
            #pragma unroll 8
            for (int i = 0; i < 32; i++) {
                const float yv = s_y[i * 128 + pp];
                acc0 = fmaf(w[wb + i],       yv, acc0);
                acc1 = fmaf(w[wb + 256 + i], yv, acc1);
                acc2 = fmaf(w[wb + 512 + i], yv, acc2);
                acc3 = fmaf(w[wb + 768 + i], yv, acc3);
            }
            s_a[t7 * 128 + pp]        = acc0;
            s_a[(8 + t7) * 128 + pp]  = acc1;
            s_a[(16 + t7) * 128 + pp] = acc2;
            s_a[(24 + t7) * 128 + pp] = acc3;
        }
        __syncthreads();

        // ---- Pass B: gate + channel-shuffled store (L2-hit re-read) ----
        const float xsv = s_xs[c];
        float4 aw = ((const float4*)(s_a + c * 128 + 64))[q];
        const float g0 = aw.x * xsv, g1 = aw.y * xsv, g2 = aw.z * xsv, g3 = aw.w * xsv;
        float4* od = (float4*)(out + ((size_t)(n * 512 + shuffle_out_ch(g * 64 + 32 + c))) * 4096);
        #pragma unroll
        for (int tt = 0; tt < 32; tt += 8) {
            float4 v[8];
            #pragma unroll
            for (int j = 0; j < 8; j++) v[j] = __ldcs(&xc4[(tt + j) * 32 + lane]);
            #pragma unroll
            for (int j = 0; j < 8; j++) {
                const float ah = s_a[c * 128 + 2 * (tt + j) + half];
                v[j].x *= sigapx_(ah * g0);
                v[j].y *= sigapx_(ah * g1);
                v[j].z *= sigapx_(ah * g2);
                v[j].w *= sigapx_(ah * g3);
                __stcs(&od[(tt + j) * 32 + lane], v[j]);
            }
        }
    }
}

extern "C" void kernel_launch(void* const* d_in, const int* in_sizes, int n_in,
                              void* d_out, int out_size) {
    const float* x       = (const float*)d_in[0];
    const float* cweight = (const float*)d_in[1];
    const float* cbias   = (const float*)d_in[2];
    const float* conv1_w = (const float*)d_in[3];
    const float* conv1_b = (const float*)d_in[4];
    const float* gn_g    = (const float*)d_in[5];
    const float* gn_b    = (const float*)d_in[6];
    const float* convh_w = (const float*)d_in[7];
    const float* convh_b = (const float*)d_in[8];
    const float* convw_w = (const float*)d_in[9];
    const float* convw_b = (const float*)d_in[10];
    float* out = (float*)d_out;

    reset_counter_k<<<1, 1>>>();
    scsa_persistent<<<NCTAS, THREADS>>>(
        x, cweight, cbias, conv1_w, conv1_b, gn_g, gn_b,
        convh_w, convh_b, convw_w, convw_b, out);
}